// round 11
// baseline (speedup 1.0000x reference)
#include <cuda_runtime.h>
#include <cuda_bf16.h>
#include <math.h>
#include <cstdint>

#define D     128
#define KM    128
#define NTOK  8192
#define BB    16
#define NTILES 1024
#define NTH   512
#define IMGB  32768
#define HB    16384

// smem slots
#define OFF_AHI 0
#define OFF_ALO 32768
#define OFF_BHI 65536
#define OFF_BLO 98304
#define OFF_XHI 131072
#define OFF_XLO 163840
#define CS_MID  131072
#define CS_BIG  196608
#define SM_MID  (CS_MID + 4096)   // 135168
#define SM_BIG  (CS_BIG + 4096)   // 200704

// ---------------- global scratch ---------------------------------------------
__device__ __align__(16) char g_himg [(size_t)NTILES*2*IMGB];
__device__ __align__(16) char g_Bimg [64*2*IMGB];
__device__ __align__(16) char g_wimg [8*2*IMGB];
__device__ __align__(16) char g_scimg[BB*2*IMGB];
__device__ float g_part[(size_t)NTILES*D*KM];   // per-tile S partials, 64 MB
__device__ float g_S   [BB*D*KM];
__device__ float g_c1t [KM*D*D];
__device__ float g_c3t [KM*D*D];
__device__ float g_colb[32*KM];

#define HIMG(t,hl)  (g_himg  + ((size_t)(t)*2 + (hl))*IMGB)
#define BIMG(t,hl)  (g_Bimg  + ((size_t)(t)*2 + (hl))*IMGB)
#define WIMG(w,hl)  (g_wimg  + ((size_t)(w)*2 + (hl))*IMGB)
#define SCIMG(b,hl) (g_scimg + ((size_t)(b)*2 + (hl))*IMGB)
// weight idx: 0 fc0_w2, 1 a0_f1w, 2 a0_f2w, 3 w1_w, 4 a2_f1w, 5 a2_f2w, 6 w3_w, 7 fc1_w

// ---------------- helpers ----------------------------------------------------
__device__ __forceinline__ uint32_t smem_u32(const void* p) {
    uint32_t a;
    asm("{ .reg .u64 t; cvta.to.shared.u64 t, %1; cvt.u32.u64 %0, t; }" : "=r"(a) : "l"(p));
    return a;
}
__device__ __forceinline__ float gelu_f(float x) {
    return 0.5f * x * (1.0f + erff(x * 0.7071067811865475f));
}
__device__ __forceinline__ uint32_t taddr(int r, int c) {
    return ((uint32_t)(c >> 6) << 14) + ((uint32_t)r << 7)
         + (uint32_t)((((c & 63) << 1)) ^ ((r & 7) << 4));
}
__device__ __forceinline__ uint32_t split_pack(float x0, float x1, uint32_t& lop) {
    __nv_bfloat16 h0 = __float2bfloat16(x0);
    __nv_bfloat16 h1 = __float2bfloat16(x1);
    __nv_bfloat16 l0 = __float2bfloat16(x0 - __bfloat162float(h0));
    __nv_bfloat16 l1 = __float2bfloat16(x1 - __bfloat162float(h1));
    __nv_bfloat162 hp; hp.x = h0; hp.y = h1;
    __nv_bfloat162 lp; lp.x = l0; lp.y = l1;
    lop = *(uint32_t*)&lp;
    return *(uint32_t*)&hp;
}
__device__ __forceinline__ float2 unpack_split(uint32_t hw, uint32_t lw) {
    __nv_bfloat162 hp = *(__nv_bfloat162*)&hw;
    __nv_bfloat162 lp = *(__nv_bfloat162*)&lw;
    return make_float2(__bfloat162float(hp.x) + __bfloat162float(lp.x),
                       __bfloat162float(hp.y) + __bfloat162float(lp.y));
}
__device__ __forceinline__ void store_split(char* ihi, char* ilo, int r, int c,
                                            float v0, float v1) {
    uint32_t lw, hw = split_pack(v0, v1, lw);
    uint32_t a = taddr(r, c);
    *(uint32_t*)(ihi + a) = hw; *(uint32_t*)(ilo + a) = lw;
}

// cp.async
__device__ __forceinline__ void cp16(uint32_t s, const void* g) {
    asm volatile("cp.async.cg.shared.global [%0], [%1], 16;" :: "r"(s), "l"(g) : "memory");
}
#define CP_COMMIT() asm volatile("cp.async.commit_group;" ::: "memory")
#define CP_WAIT0()  asm volatile("cp.async.wait_group 0;" ::: "memory")
#define CP_WAIT1()  asm volatile("cp.async.wait_group 1;" ::: "memory")
__device__ __forceinline__ void cpimg_h(uint32_t sdst, const char* g, int half, int tid) {
    uint32_t off = (uint32_t)half * HB;
    for (int i = tid; i < 1024; i += NTH) cp16(sdst + off + i * 16, g + off + i * 16);
}
__device__ __forceinline__ void cpimg(uint32_t sdst, const char* g, int tid) {
    for (int i = tid; i < 2048; i += NTH) cp16(sdst + i * 16, g + i * 16);
}

// ldmatrix / mma
__device__ __forceinline__ void ldsm4(uint32_t a[4], uint32_t addr) {
    asm volatile("ldmatrix.sync.aligned.m8n8.x4.shared.b16 {%0,%1,%2,%3}, [%4];"
        : "=r"(a[0]), "=r"(a[1]), "=r"(a[2]), "=r"(a[3]) : "r"(addr));
}
__device__ __forceinline__ void ldsm4t(uint32_t a[4], uint32_t addr) {
    asm volatile("ldmatrix.sync.aligned.m8n8.x4.trans.shared.b16 {%0,%1,%2,%3}, [%4];"
        : "=r"(a[0]), "=r"(a[1]), "=r"(a[2]), "=r"(a[3]) : "r"(addr));
}
__device__ __forceinline__ void mma16816(float c[4], const uint32_t a[4], const uint32_t* b) {
    asm volatile("mma.sync.aligned.m16n8k16.row.col.f32.bf16.bf16.f32 "
        "{%0,%1,%2,%3}, {%4,%5,%6,%7}, {%8,%9}, {%0,%1,%2,%3};"
        : "+f"(c[0]), "+f"(c[1]), "+f"(c[2]), "+f"(c[3])
        : "r"(a[0]), "r"(a[1]), "r"(a[2]), "r"(a[3]), "r"(b[0]), "r"(b[1]));
}

// one k-half (64 cols) of C[m][n] += A[m][k] B[n][k]; B via batched x4.
__device__ __forceinline__ void gemm_h(uint32_t sAhi, uint32_t sAlo,
                                       uint32_t sBhi, uint32_t sBlo,
                                       float acc[2][4][4], int lane, int m0, int n0, int kbeg) {
#pragma unroll
    for (int k0 = kbeg; k0 < kbeg + 64; k0 += 16) {
        uint32_t aoff  = taddr(m0 + (lane & 15), k0 + ((lane >> 4) << 3));
        uint32_t aoff2 = taddr(m0 + 16 + (lane & 15), k0 + ((lane >> 4) << 3));
        uint32_t ah0[4], ah1[4], al0[4], al1[4];
        ldsm4(ah0, sAhi + aoff);  ldsm4(ah1, sAhi + aoff2);
        ldsm4(al0, sAlo + aoff);  ldsm4(al1, sAlo + aoff2);
        uint32_t bh[8], bl[8];
#pragma unroll
        for (int jj = 0; jj < 2; jj++) {
            uint32_t boff = taddr(n0 + jj * 16 + ((lane >> 4) << 3) + (lane & 7),
                                  k0 + (((lane >> 3) & 1) << 3));
            ldsm4(bh + jj * 4, sBhi + boff);
            ldsm4(bl + jj * 4, sBlo + boff);
        }
#pragma unroll
        for (int j = 0; j < 4; j++) {
            mma16816(acc[0][j], ah0, bh + j * 2); mma16816(acc[1][j], ah1, bh + j * 2);
            mma16816(acc[0][j], ah0, bl + j * 2); mma16816(acc[1][j], ah1, bl + j * 2);
            mma16816(acc[0][j], al0, bh + j * 2); mma16816(acc[1][j], al1, bh + j * 2);
        }
    }
}

// one k-half (64 ROWS) of C[m][n] += A[t][m] B[t][n] (t-major, trans ldmatrix)
__device__ __forceinline__ void gemm_tt_h(uint32_t sAhi, uint32_t sAlo,
                                          uint32_t sBhi, uint32_t sBlo,
                                          float acc[2][4][4], int lane, int m0, int n0, int kbeg) {
#pragma unroll
    for (int k0 = kbeg; k0 < kbeg + 64; k0 += 16) {
        int arow = k0 + (lane & 7) + ((lane >> 4) << 3);
        int acol = ((lane >> 3) & 1) << 3;
        uint32_t aoff  = taddr(arow, m0 + acol);
        uint32_t aoff2 = taddr(arow, m0 + 16 + acol);
        uint32_t ah0[4], ah1[4], al0[4], al1[4];
        ldsm4t(ah0, sAhi + aoff);  ldsm4t(ah1, sAhi + aoff2);
        ldsm4t(al0, sAlo + aoff);  ldsm4t(al1, sAlo + aoff2);
        uint32_t bh[8], bl[8];
#pragma unroll
        for (int jj = 0; jj < 2; jj++) {
            uint32_t boff = taddr(k0 + (lane & 7) + (((lane >> 3) & 1) << 3),
                                  n0 + jj * 16 + ((lane >> 4) << 3));
            ldsm4t(bh + jj * 4, sBhi + boff);
            ldsm4t(bl + jj * 4, sBlo + boff);
        }
#pragma unroll
        for (int j = 0; j < 4; j++) {
            mma16816(acc[0][j], ah0, bh + j * 2); mma16816(acc[1][j], ah1, bh + j * 2);
            mma16816(acc[0][j], ah0, bl + j * 2); mma16816(acc[1][j], ah1, bl + j * 2);
            mma16816(acc[0][j], al0, bh + j * 2); mma16816(acc[1][j], al1, bh + j * 2);
        }
    }
}

// fused S-partial: part[tile][c][k] = sum_t hout[t][c] * B[t][k]
__device__ __forceinline__ void fused_reduce(uint32_t sHhi, uint32_t sHlo,
                                             uint32_t sTBhi, uint32_t sTBlo,
                                             int tile, int lane, int m0, int n0,
                                             int qr, int qc) {
    float acc[2][4][4] = {};
    gemm_tt_h(sHhi, sHlo, sTBhi, sTBlo, acc, lane, m0, n0, 0);
    gemm_tt_h(sHhi, sHlo, sTBhi, sTBlo, acc, lane, m0, n0, 64);
    size_t ob = (size_t)tile * D * KM;
#pragma unroll
    for (int mt = 0; mt < 2; mt++)
#pragma unroll
        for (int j = 0; j < 4; j++) {
            int row = m0 + mt * 16 + qr, col = n0 + j * 8 + qc;
            *(float2*)&g_part[ob + (size_t)row * KM + col]       = make_float2(acc[mt][j][0], acc[mt][j][1]);
            *(float2*)&g_part[ob + (size_t)(row + 8) * KM + col] = make_float2(acc[mt][j][2], acc[mt][j][3]);
        }
}

#define WARP_SETUP()                                                 \
    int tid = threadIdx.x;                                           \
    int lane = tid & 31, wid = tid >> 5;                             \
    int m0 = (wid & 3) * 32, n0 = (wid >> 2) * 32;                   \
    int qr = lane >> 2, qc = (lane & 3) * 2;                         \
    (void)qr; (void)qc;

#define TILE_PTRS(CS)                                                \
    extern __shared__ __align__(1024) char dsm[];                    \
    char* Ahi = dsm + OFF_AHI; char* Alo = dsm + OFF_ALO;            \
    char* Xhi = dsm + OFF_XHI; char* Xlo = dsm + OFF_XLO;            \
    uint32_t sb = smem_u32(dsm);                                     \
    uint32_t sAhi = sb + OFF_AHI, sAlo = sb + OFF_ALO;               \
    uint32_t sBhi = sb + OFF_BHI, sBlo = sb + OFF_BLO;               \
    float* ctrl = (float*)(dsm + (CS));                              \
    (void)Ahi; (void)Alo; (void)Xhi; (void)Xlo; (void)ctrl;

// ---------------- prep kernels -----------------------------------------------
__global__ void colb_kernel(const float* __restrict__ Bm) {
    int k = threadIdx.x, p = blockIdx.x;
    float s = 0.f;
    int r0 = p * 256;
    for (int r = 0; r < 256; r++) s += Bm[(r0 + r) * KM + k];
    g_colb[p * KM + k] = s;
}
__global__ void transpose_w_kernel(const float* __restrict__ W, int which) {
    float* Wt = which ? g_c3t : g_c1t;
    __shared__ float tile[32][33];
    int x0 = blockIdx.x * 32, y0 = blockIdx.y * 32;
    int tx = threadIdx.x, ty = threadIdx.y;
#pragma unroll
    for (int r = 0; r < 32; r += 8)
        tile[ty + r][tx] = W[(x0 + ty + r) * KM + y0 + tx];
    __syncthreads();
#pragma unroll
    for (int r = 0; r < 32; r += 8)
        Wt[(y0 + ty + r) * (D * D) + x0 + tx] = tile[tx][ty + r];
}
__global__ void split_w_kernel(const float* __restrict__ W, int widx) {
    int p = blockIdx.x * 256 + threadIdx.x;
    int r = p >> 6, c = (p & 63) << 1;
    store_split(WIMG(widx, 0), WIMG(widx, 1), r, c, W[c * D + r], W[(c + 1) * D + r]);
}
__global__ void split_B_kernel(const float* __restrict__ Bm) {
    int tile = blockIdx.x;
    for (int p = threadIdx.x; p < 8192; p += 256) {
        int r = p >> 6, c = (p & 63) << 1;
        float2 v = *(const float2*)(Bm + (size_t)(tile * 128 + r) * KM + c);
        store_split(BIMG(tile, 0), BIMG(tile, 1), r, c, v.x, v.y);
    }
}
// sum 64 per-tile partials -> S[b]
__global__ void reduce2_kernel() {
    int e = blockIdx.x * 256 + threadIdx.x;
    int b = blockIdx.y;
    const float* p = g_part + (size_t)b * 64 * D * KM + e;
    float s = 0.f;
#pragma unroll 8
    for (int t = 0; t < 64; t++) s += p[(size_t)t * D * KM];
    g_S[b * D * KM + e] = s;
}

#define AST 132
__device__ __forceinline__ void gemm8x8(const float* __restrict__ A, const float* __restrict__ W,
                                        float (&acc)[8][8], int ty, int tx, int kdim) {
    const float* ap = A + ty * 8;
    const float* wp = W + tx * 8;
#pragma unroll 4
    for (int k = 0; k < kdim; k++) {
        float4 a0 = *(const float4*)(ap + k * AST);
        float4 a1 = *(const float4*)(ap + k * AST + 4);
        float4 w0 = *(const float4*)(wp + k * AST);
        float4 w1 = *(const float4*)(wp + k * AST + 4);
        float a[8] = {a0.x,a0.y,a0.z,a0.w,a1.x,a1.y,a1.z,a1.w};
        float w[8] = {w0.x,w0.y,w0.z,w0.w,w1.x,w1.y,w1.z,w1.w};
#pragma unroll
        for (int i = 0; i < 8; i++)
#pragma unroll
            for (int j = 0; j < 8; j++)
                acc[i][j] = fmaf(a[i], w[j], acc[i][j]);
    }
}

__global__ void score_kernel(const float* __restrict__ wk, const float* __restrict__ bk) {
    extern __shared__ float sm[];
    float* As = sm;
    float* Ws = sm + D * AST;
    float* cb = Ws + D * AST;
    float* bks = cb + 128;
    int b = blockIdx.x, tid = threadIdx.x;
    if (tid < KM) {
        float s = 0.f;
        for (int p = 0; p < 32; p++) s += g_colb[p * KM + tid];
        cb[tid] = s;
        bks[tid] = bk[tid];
    }
    for (int idx = tid; idx < D * D; idx += 256) {
        As[(idx >> 7) * AST + (idx & 127)] = wk[idx];
        Ws[(idx >> 7) * AST + (idx & 127)] = g_S[b * D * KM + idx];
    }
    __syncthreads();
    int ty = tid >> 4, tx = tid & 15;
    float acc[8][8] = {};
    gemm8x8(As, Ws, acc, ty, tx, D);
#pragma unroll
    for (int j = 0; j < 8; j++) {
        int r = tx * 8 + j;
        float cbv = cb[r];
#pragma unroll
        for (int i = 0; i < 8; i += 2) {
            float v0 = acc[i][j]     + bks[ty * 8 + i]     * cbv;
            float v1 = acc[i + 1][j] + bks[ty * 8 + i + 1] * cbv;
            store_split(SCIMG(b, 0), SCIMG(b, 1), r, ty * 8 + i, v0, v1);
        }
    }
}

__global__ void gconv_modes_kernel(int which) {
    const float* Wt = which ? g_c3t : g_c1t;
    __shared__ float Ss[BB * D];
    int k = blockIdx.x, tid = threadIdx.x;
    for (int idx = tid; idx < BB * D; idx += 256)
        Ss[idx] = g_S[((idx >> 7) * D + (idx & 127)) * KM + k];
    __syncthreads();
    int hi = tid >> 7, o = tid & 127;
    float acc[8] = {};
    for (int i = 0; i < D; i++) {
        float w = Wt[(k * D + i) * D + o];
#pragma unroll
        for (int q = 0; q < 8; q++)
            acc[q] = fmaf(Ss[(hi * 8 + q) * D + i], w, acc[q]);
    }
    uint32_t a = taddr(o, k);
#pragma unroll
    for (int q = 0; q < 8; q++) {
        int bi = hi * 8 + q;
        __nv_bfloat16 hb = __float2bfloat16(acc[q]);
        __nv_bfloat16 lb = __float2bfloat16(acc[q] - __bfloat162float(hb));
        *(uint16_t*)(SCIMG(bi, 0) + a) = *(uint16_t*)&hb;
        *(uint16_t*)(SCIMG(bi, 1) + a) = *(uint16_t*)&lb;
    }
}

// ---------------- fc0 (+ fused S partial) -------------------------------------
__global__ __launch_bounds__(NTH, 1)
void fc0_kernel(const float* __restrict__ x, const float* __restrict__ w1,
                const float* __restrict__ b1, const float* __restrict__ b2) {
    TILE_PTRS(CS_MID); WARP_SETUP();
    float* xs  = ctrl;
    float* w1s = ctrl + 256;
    float* b1s = ctrl + 512;
    float* b2s = ctrl + 640;
    int tile = blockIdx.x;
    int tok0 = tile * 128;
    int tb = tile & 63;

    cpimg_h(sBhi, WIMG(0, 0), 0, tid); cpimg_h(sBlo, WIMG(0, 1), 0, tid); CP_COMMIT();
    cpimg_h(sBhi, WIMG(0, 0), 1, tid); cpimg_h(sBlo, WIMG(0, 1), 1, tid); CP_COMMIT();
    if (tid < 256) { xs[tid] = x[tok0 * 2 + tid]; w1s[tid] = w1[tid]; }
    if (tid < 128) { b1s[tid] = b1[tid]; b2s[tid] = b2[tid]; }
    __syncthreads();

    for (int p = tid; p < 128 * 64; p += NTH) {
        int r = p >> 6, c = (p & 63) << 1;
        float v0 = gelu_f(xs[2*r] * w1s[c]   + xs[2*r+1] * w1s[128+c]   + b1s[c]);
        float v1 = gelu_f(xs[2*r] * w1s[c+1] + xs[2*r+1] * w1s[128+c+1] + b1s[c+1]);
        uint32_t lw, hw = split_pack(v0, v1, lw);
        uint32_t a = taddr(r, c);
        *(uint32_t*)(Ahi + a) = hw; *(uint32_t*)(Alo + a) = lw;
    }
    CP_WAIT1(); __syncthreads();

    float acc[2][4][4] = {};
    gemm_h(sAhi, sAlo, sBhi, sBlo, acc, lane, m0, n0, 0);
    CP_WAIT0(); __syncthreads();
    gemm_h(sAhi, sAlo, sBhi, sBlo, acc, lane, m0, n0, 64);
    __syncthreads();

    // prefetch B-tile into B slots (weights dead)
    cpimg(sBhi, BIMG(tb, 0), tid); cpimg(sBlo, BIMG(tb, 1), tid); CP_COMMIT();

    // epilogue: out -> global himg + A slots (as [t][c] image)
    char* oh = HIMG(tile, 0); char* ol = HIMG(tile, 1);
#pragma unroll
    for (int mt = 0; mt < 2; mt++)
#pragma unroll
        for (int j = 0; j < 4; j++) {
            int row = m0 + mt * 16 + qr, col = n0 + j * 8 + qc;
#pragma unroll
            for (int h = 0; h < 2; h++) {
                int r = row + h * 8;
                float o0 = acc[mt][j][2*h]   + b2s[col];
                float o1 = acc[mt][j][2*h+1] + b2s[col + 1];
                uint32_t lw, hw = split_pack(o0, o1, lw);
                uint32_t a = taddr(r, col);
                *(uint32_t*)(oh + a) = hw;  *(uint32_t*)(ol + a) = lw;
                *(uint32_t*)(Ahi + a) = hw; *(uint32_t*)(Alo + a) = lw;
            }
        }
    CP_WAIT0(); __syncthreads();
    fused_reduce(sAhi, sAlo, sBhi, sBlo, tile, lane, m0, n0, qr, qc);
}

// ---------------- attention map (3 chained GEMMs + fused S) ------------------
__global__ __launch_bounds__(NTH, 1)
void attn_map_kernel(int wbase, const float* __restrict__ f1b, const float* __restrict__ f2b) {
    TILE_PTRS(CS_BIG); WARP_SETUP();
    uint32_t sXhi = sb + OFF_XHI, sXlo = sb + OFF_XLO;
    int b = blockIdx.x >> 6;
    int tile = blockIdx.x;
    int tb = tile & 63;

    if (tid < 128) { ctrl[tid] = f1b[tid]; ctrl[128 + tid] = f2b[tid]; }
    cpimg_h(sAhi, BIMG(tb, 0), 0, tid); cpimg_h(sAlo, BIMG(tb, 1), 0, tid);
    cpimg_h(sBhi, SCIMG(b, 0), 0, tid); cpimg_h(sBlo, SCIMG(b, 1), 0, tid);
    CP_COMMIT();
    cpimg_h(sAhi, BIMG(tb, 0), 1, tid); cpimg_h(sAlo, BIMG(tb, 1), 1, tid);
    cpimg_h(sBhi, SCIMG(b, 0), 1, tid); cpimg_h(sBlo, SCIMG(b, 1), 1, tid);
    cpimg(sXhi, HIMG(tile, 0), tid);    cpimg(sXlo, HIMG(tile, 1), tid);
    CP_COMMIT();

    float acc[2][4][4] = {};
    CP_WAIT1(); __syncthreads();
    gemm_h(sAhi, sAlo, sBhi, sBlo, acc, lane, m0, n0, 0);        // GEMM1.h0
    __syncthreads();
    cpimg_h(sBhi, WIMG(wbase, 0), 0, tid); cpimg_h(sBlo, WIMG(wbase, 1), 0, tid); CP_COMMIT();
    CP_WAIT1(); __syncthreads();
    gemm_h(sAhi, sAlo, sBhi, sBlo, acc, lane, m0, n0, 64);       // GEMM1.h1
    __syncthreads();
    cpimg_h(sBhi, WIMG(wbase, 0), 1, tid); cpimg_h(sBlo, WIMG(wbase, 1), 1, tid); CP_COMMIT();

    // ep1: xt = gelu(attn) + h -> A (operand) and X (residual keep)
#pragma unroll
    for (int mt = 0; mt < 2; mt++)
#pragma unroll
        for (int j = 0; j < 4; j++) {
            int row = m0 + mt * 16 + qr, col = n0 + j * 8 + qc;
#pragma unroll
            for (int h = 0; h < 2; h++) {
                int r = row + h * 8;
                uint32_t a = taddr(r, col);
                float2 hh = unpack_split(*(uint32_t*)(Xhi + a), *(uint32_t*)(Xlo + a));
                float x0 = gelu_f(acc[mt][j][2*h])   + hh.x;
                float x1 = gelu_f(acc[mt][j][2*h+1]) + hh.y;
                uint32_t lw, hw = split_pack(x0, x1, lw);
                *(uint32_t*)(Ahi + a) = hw; *(uint32_t*)(Alo + a) = lw;
                *(uint32_t*)(Xhi + a) = hw; *(uint32_t*)(Xlo + a) = lw;
            }
        }

    float acc2[2][4][4] = {};
    CP_WAIT1(); __syncthreads();
    gemm_h(sAhi, sAlo, sBhi, sBlo, acc2, lane, m0, n0, 0);       // GEMM2.h0
    __syncthreads();
    cpimg_h(sBhi, WIMG(wbase + 1, 0), 0, tid); cpimg_h(sBlo, WIMG(wbase + 1, 1), 0, tid); CP_COMMIT();
    CP_WAIT1(); __syncthreads();
    gemm_h(sAhi, sAlo, sBhi, sBlo, acc2, lane, m0, n0, 64);      // GEMM2.h1
    __syncthreads();
    cpimg_h(sBhi, WIMG(wbase + 1, 0), 1, tid); cpimg_h(sBlo, WIMG(wbase + 1, 1), 1, tid); CP_COMMIT();

    // ep2: g = gelu(u + f1b) -> A
#pragma unroll
    for (int mt = 0; mt < 2; mt++)
#pragma unroll
        for (int j = 0; j < 4; j++) {
            int row = m0 + mt * 16 + qr, col = n0 + j * 8 + qc;
#pragma unroll
            for (int h = 0; h < 2; h++) {
                int r = row + h * 8;
                float g0 = gelu_f(acc2[mt][j][2*h]   + ctrl[col]);
                float g1 = gelu_f(acc2[mt][j][2*h+1] + ctrl[col + 1]);
                uint32_t lw, hw = split_pack(g0, g1, lw);
                uint32_t a = taddr(r, col);
                *(uint32_t*)(Ahi + a) = hw; *(uint32_t*)(Alo + a) = lw;
            }
        }

    float acc3[2][4][4] = {};
    CP_WAIT1(); __syncthreads();
    gemm_h(sAhi, sAlo, sBhi, sBlo, acc3, lane, m0, n0, 0);       // GEMM3.h0
    CP_WAIT0(); __syncthreads();
    gemm_h(sAhi, sAlo, sBhi, sBlo, acc3, lane, m0, n0, 64);      // GEMM3.h1
    __syncthreads();

    // prefetch B-tile into A slots (g dead)
    cpimg(sAhi, BIMG(tb, 0), tid); cpimg(sAlo, BIMG(tb, 1), tid); CP_COMMIT();

    // ep3: final = xt + r + f2b -> global himg + X slots
    char* oh = HIMG(tile, 0); char* ol = HIMG(tile, 1);
#pragma unroll
    for (int mt = 0; mt < 2; mt++)
#pragma unroll
        for (int j = 0; j < 4; j++) {
            int row = m0 + mt * 16 + qr, col = n0 + j * 8 + qc;
#pragma unroll
            for (int h = 0; h < 2; h++) {
                int r = row + h * 8;
                uint32_t a = taddr(r, col);
                float2 xt = unpack_split(*(uint32_t*)(Xhi + a), *(uint32_t*)(Xlo + a));
                float o0 = xt.x + acc3[mt][j][2*h]   + ctrl[128 + col];
                float o1 = xt.y + acc3[mt][j][2*h+1] + ctrl[128 + col + 1];
                uint32_t lw, hw = split_pack(o0, o1, lw);
                *(uint32_t*)(oh + a) = hw;  *(uint32_t*)(ol + a) = lw;
                *(uint32_t*)(Xhi + a) = hw; *(uint32_t*)(Xlo + a) = lw;
            }
        }
    CP_WAIT0(); __syncthreads();
    fused_reduce(sXhi, sXlo, sAhi, sAlo, tile, lane, m0, n0, qr, qc);
}

// ---------------- gconv map (2 GEMMs + optional fused S) ---------------------
__global__ __launch_bounds__(NTH, 1)
void gconv_map_kernel(int widx, const float* __restrict__ wb, int act, int do_red) {
    TILE_PTRS(CS_MID); WARP_SETUP();
    int b = blockIdx.x >> 6;
    int tile = blockIdx.x;
    int tb = tile & 63;

    if (tid < 128) ctrl[tid] = wb[tid];
    cpimg_h(sAhi, BIMG(tb, 0), 0, tid); cpimg_h(sAlo, BIMG(tb, 1), 0, tid);
    cpimg_h(sBhi, SCIMG(b, 0), 0, tid); cpimg_h(sBlo, SCIMG(b, 1), 0, tid);
    CP_COMMIT();
    cpimg_h(sAhi, BIMG(tb, 0), 1, tid); cpimg_h(sAlo, BIMG(tb, 1), 1, tid);
    cpimg_h(sBhi, SCIMG(b, 0), 1, tid); cpimg_h(sBlo, SCIMG(b, 1), 1, tid);
    CP_COMMIT();

    float acc[2][4][4] = {};
    CP_WAIT1(); __syncthreads();
    gemm_h(sAhi, sAlo, sBhi, sBlo, acc, lane, m0, n0, 0);        // GEMM1.h0
    __syncthreads();
    cpimg_h(sAhi, HIMG(tile, 0), 0, tid); cpimg_h(sAlo, HIMG(tile, 1), 0, tid);
    cpimg_h(sBhi, WIMG(widx, 0), 0, tid); cpimg_h(sBlo, WIMG(widx, 1), 0, tid);
    CP_COMMIT();
    CP_WAIT1(); __syncthreads();
    gemm_h(sAhi, sAlo, sBhi, sBlo, acc, lane, m0, n0, 64);       // GEMM1.h1
    __syncthreads();
    cpimg_h(sAhi, HIMG(tile, 0), 1, tid); cpimg_h(sAlo, HIMG(tile, 1), 1, tid);
    cpimg_h(sBhi, WIMG(widx, 0), 1, tid); cpimg_h(sBlo, WIMG(widx, 1), 1, tid);
    CP_COMMIT();
    CP_WAIT1(); __syncthreads();
    gemm_h(sAhi, sAlo, sBhi, sBlo, acc, lane, m0, n0, 0);        // GEMM2.h0
    CP_WAIT0(); __syncthreads();
    gemm_h(sAhi, sAlo, sBhi, sBlo, acc, lane, m0, n0, 64);       // GEMM2.h1
    __syncthreads();

    if (do_red) { cpimg(sBhi, BIMG(tb, 0), tid); cpimg(sBlo, BIMG(tb, 1), tid); CP_COMMIT(); }

    // epilogue: out = h + act(z) -> global himg + A slots
    char* oh = HIMG(tile, 0); char* ol = HIMG(tile, 1);
#pragma unroll
    for (int mt = 0; mt < 2; mt++)
#pragma unroll
        for (int j = 0; j < 4; j++) {
            int row = m0 + mt * 16 + qr, col = n0 + j * 8 + qc;
#pragma unroll
            for (int h = 0; h < 2; h++) {
                int r = row + h * 8;
                uint32_t a = taddr(r, col);
                float2 hh = unpack_split(*(uint32_t*)(Ahi + a), *(uint32_t*)(Alo + a));
                float z0 = acc[mt][j][2*h]   + ctrl[col];
                float z1 = acc[mt][j][2*h+1] + ctrl[col + 1];
                if (act) { z0 = gelu_f(z0); z1 = gelu_f(z1); }
                float o0 = hh.x + z0, o1 = hh.y + z1;
                uint32_t lw, hw = split_pack(o0, o1, lw);
                *(uint32_t*)(oh + a) = hw;  *(uint32_t*)(ol + a) = lw;
                *(uint32_t*)(Ahi + a) = hw; *(uint32_t*)(Alo + a) = lw;
            }
        }
    if (do_red) {
        CP_WAIT0(); __syncthreads();
        fused_reduce(sAhi, sAlo, sBhi, sBlo, tile, lane, m0, n0, qr, qc);
    }
}

// ---------------- head --------------------------------------------------------
__global__ __launch_bounds__(NTH, 1)
void head_kernel(const float* __restrict__ fc1b, const float* __restrict__ fc2w,
                 const float* __restrict__ fc2b, float* __restrict__ out) {
    TILE_PTRS(CS_MID); WARP_SETUP();
    int tile = blockIdx.x;
    size_t tok0 = (size_t)tile * 128;
    int wn = wid >> 2;

    if (tid < 128) { ctrl[tid] = fc1b[tid]; ctrl[128 + tid] = fc2w[tid]; }
    float* partial = ctrl + 256;
    cpimg_h(sAhi, HIMG(tile, 0), 0, tid); cpimg_h(sAlo, HIMG(tile, 1), 0, tid);
    cpimg_h(sBhi, WIMG(7, 0), 0, tid);    cpimg_h(sBlo, WIMG(7, 1), 0, tid);
    CP_COMMIT();
    cpimg_h(sAhi, HIMG(tile, 0), 1, tid); cpimg_h(sAlo, HIMG(tile, 1), 1, tid);
    cpimg_h(sBhi, WIMG(7, 0), 1, tid);    cpimg_h(sBlo, WIMG(7, 1), 1, tid);
    CP_COMMIT();

    float acc[2][4][4] = {};
    CP_WAIT1(); __syncthreads();
    gemm_h(sAhi, sAlo, sBhi, sBlo, acc, lane, m0, n0, 0);
    CP_WAIT0(); __syncthreads();
    gemm_h(sAhi, sAlo, sBhi, sBlo, acc, lane, m0, n0, 64);

    float s[2][2] = {};
#pragma unroll
    for (int mt = 0; mt < 2; mt++)
#pragma unroll
        for (int j = 0; j < 4; j++) {
            int col = n0 + j * 8 + qc;
            s[mt][0] += gelu_f(acc[mt][j][0] + ctrl[col])     * ctrl[128 + col]
                      + gelu_f(acc[mt][j][1] + ctrl[col + 1]) * ctrl[128 + col + 1];
            s[mt][1] += gelu_f(acc[mt][j][2] + ctrl[col])     * ctrl[128 + col]
                      + gelu_f(acc[mt][j][3] + ctrl[col + 1]) * ctrl[128 + col + 1];
        }
#pragma unroll
    for (int mt = 0; mt < 2; mt++)
#pragma unroll
        for (int h = 0; h < 2; h++) {
            s[mt][h] += __shfl_xor_sync(0xffffffffu, s[mt][h], 1);
            s[mt][h] += __shfl_xor_sync(0xffffffffu, s[mt][h], 2);
        }
    if ((lane & 3) == 0) {
#pragma unroll
        for (int mt = 0; mt < 2; mt++) {
            partial[wn * 128 + m0 + mt * 16 + qr]     = s[mt][0];
            partial[wn * 128 + m0 + mt * 16 + qr + 8] = s[mt][1];
        }
    }
    __syncthreads();
    if (tid < 128)
        out[tok0 + tid] = partial[tid] + partial[128 + tid] + partial[256 + tid]
                        + partial[384 + tid] + fc2b[0];
}

// ---------------- launch ------------------------------------------------------
extern "C" void kernel_launch(void* const* d_in, const int* in_sizes, int n_in,
                              void* d_out, int out_size) {
    const float* x      = (const float*)d_in[0];
    const float* Bm     = (const float*)d_in[1];
    const float* fc0_w1 = (const float*)d_in[2];
    const float* fc0_b1 = (const float*)d_in[3];
    const float* fc0_w2 = (const float*)d_in[4];
    const float* fc0_b2 = (const float*)d_in[5];
    const float* a0_wk  = (const float*)d_in[6];
    const float* a0_bk  = (const float*)d_in[7];
    const float* a0_f1w = (const float*)d_in[8];
    const float* a0_f1b = (const float*)d_in[9];
    const float* a0_f2w = (const float*)d_in[10];
    const float* a0_f2b = (const float*)d_in[11];
    const float* c1_w   = (const float*)d_in[12];
    const float* w1_w   = (const float*)d_in[13];
    const float* w1_b   = (const float*)d_in[14];
    const float* a2_wk  = (const float*)d_in[15];
    const float* a2_bk  = (const float*)d_in[16];
    const float* a2_f1w = (const float*)d_in[17];
    const float* a2_f1b = (const float*)d_in[18];
    const float* a2_f2w = (const float*)d_in[19];
    const float* a2_f2b = (const float*)d_in[20];
    const float* c3_w   = (const float*)d_in[21];
    const float* w3_w   = (const float*)d_in[22];
    const float* w3_b   = (const float*)d_in[23];
    const float* fc1_w  = (const float*)d_in[24];
    const float* fc1_b  = (const float*)d_in[25];
    const float* fc2_w  = (const float*)d_in[26];
    const float* fc2_b  = (const float*)d_in[27];
    float* out = (float*)d_out;

    const int SM2 = (2 * D * AST + 1024) * sizeof(float);
    cudaFuncSetAttribute((const void*)fc0_kernel,       cudaFuncAttributeMaxDynamicSharedMemorySize, SM_MID);
    cudaFuncSetAttribute((const void*)attn_map_kernel,  cudaFuncAttributeMaxDynamicSharedMemorySize, SM_BIG);
    cudaFuncSetAttribute((const void*)gconv_map_kernel, cudaFuncAttributeMaxDynamicSharedMemorySize, SM_MID);
    cudaFuncSetAttribute((const void*)head_kernel,      cudaFuncAttributeMaxDynamicSharedMemorySize, SM_MID);
    cudaFuncSetAttribute((const void*)score_kernel,     cudaFuncAttributeMaxDynamicSharedMemorySize, SM2);

    colb_kernel<<<32, 128>>>(Bm);
    transpose_w_kernel<<<dim3(512, 4), dim3(32, 8)>>>(c1_w, 0);
    transpose_w_kernel<<<dim3(512, 4), dim3(32, 8)>>>(c3_w, 1);
    split_B_kernel<<<64, 256>>>(Bm);
    split_w_kernel<<<32, 256>>>(fc0_w2, 0);
    split_w_kernel<<<32, 256>>>(a0_f1w, 1);
    split_w_kernel<<<32, 256>>>(a0_f2w, 2);
    split_w_kernel<<<32, 256>>>(w1_w,   3);
    split_w_kernel<<<32, 256>>>(a2_f1w, 4);
    split_w_kernel<<<32, 256>>>(a2_f2w, 5);
    split_w_kernel<<<32, 256>>>(w3_w,   6);
    split_w_kernel<<<32, 256>>>(fc1_w,  7);

    fc0_kernel<<<NTILES, NTH, SM_MID>>>(x, fc0_w1, fc0_b1, fc0_b2);

    reduce2_kernel<<<dim3(64, BB), 256>>>();
    score_kernel<<<BB, 256, SM2>>>(a0_wk, a0_bk);
    attn_map_kernel<<<NTILES, NTH, SM_BIG>>>(1, a0_f1b, a0_f2b);

    reduce2_kernel<<<dim3(64, BB), 256>>>();
    gconv_modes_kernel<<<KM, 256>>>(0);
    gconv_map_kernel<<<NTILES, NTH, SM_MID>>>(3, w1_b, 1, 1);

    reduce2_kernel<<<dim3(64, BB), 256>>>();
    score_kernel<<<BB, 256, SM2>>>(a2_wk, a2_bk);
    attn_map_kernel<<<NTILES, NTH, SM_BIG>>>(4, a2_f1b, a2_f2b);

    reduce2_kernel<<<dim3(64, BB), 256>>>();
    gconv_modes_kernel<<<KM, 256>>>(1);
    gconv_map_kernel<<<NTILES, NTH, SM_MID>>>(6, w3_b, 0, 0);

    head_kernel<<<NTILES, NTH, SM_MID>>>(fc1_b, fc2_w, fc2_b, out);
}

// round 12
// speedup vs baseline: 1.0132x; 1.0132x over previous
#include <cuda_runtime.h>
#include <cuda_bf16.h>
#include <math.h>
#include <cstdint>

#define D     128
#define KM    128
#define NTOK  8192
#define BB    16
#define NTILES 1024
#define NTH   512
#define IMGB  32768
#define HB    16384

// smem slots
#define OFF_AHI 0
#define OFF_ALO 32768
#define OFF_BHI 65536
#define OFF_BLO 98304
#define OFF_XHI 131072
#define OFF_XLO 163840
#define CS_MID  131072
#define CS_BIG  196608
#define SM_MID  (CS_MID + 4096)   // 135168
#define SM_BIG  (CS_BIG + 4096)   // 200704

// ---------------- global scratch ---------------------------------------------
__device__ __align__(16) char g_himg [(size_t)NTILES*2*IMGB];
__device__ __align__(16) char g_Bimg [64*2*IMGB];
__device__ __align__(16) char g_wimg [8*2*IMGB];
__device__ __align__(16) char g_scimg[BB*2*IMGB];
__device__ float g_part[(size_t)NTILES*D*KM];
__device__ float g_S   [BB*D*KM];
__device__ float g_c1t [KM*D*D];
__device__ float g_c3t [KM*D*D];
__device__ float g_colb[32*KM];

#define HIMG(t,hl)  (g_himg  + ((size_t)(t)*2 + (hl))*IMGB)
#define BIMG(t,hl)  (g_Bimg  + ((size_t)(t)*2 + (hl))*IMGB)
#define WIMG(w,hl)  (g_wimg  + ((size_t)(w)*2 + (hl))*IMGB)
#define SCIMG(b,hl) (g_scimg + ((size_t)(b)*2 + (hl))*IMGB)
// weight idx: 0 fc0_w2, 1 a0_f1w, 2 a0_f2w, 3 w1_w, 4 a2_f1w, 5 a2_f2w, 6 w3_w, 7 fc1_w

// ---------------- helpers ----------------------------------------------------
__device__ __forceinline__ uint32_t smem_u32(const void* p) {
    uint32_t a;
    asm("{ .reg .u64 t; cvta.to.shared.u64 t, %1; cvt.u32.u64 %0, t; }" : "=r"(a) : "l"(p));
    return a;
}
__device__ __forceinline__ float gelu_f(float x) {
    return 0.5f * x * (1.0f + erff(x * 0.7071067811865475f));
}
__device__ __forceinline__ uint32_t taddr(int r, int c) {
    return ((uint32_t)(c >> 6) << 14) + ((uint32_t)r << 7)
         + (uint32_t)((((c & 63) << 1)) ^ ((r & 7) << 4));
}
__device__ __forceinline__ uint32_t split_pack(float x0, float x1, uint32_t& lop) {
    __nv_bfloat16 h0 = __float2bfloat16(x0);
    __nv_bfloat16 h1 = __float2bfloat16(x1);
    __nv_bfloat16 l0 = __float2bfloat16(x0 - __bfloat162float(h0));
    __nv_bfloat16 l1 = __float2bfloat16(x1 - __bfloat162float(h1));
    __nv_bfloat162 hp; hp.x = h0; hp.y = h1;
    __nv_bfloat162 lp; lp.x = l0; lp.y = l1;
    lop = *(uint32_t*)&lp;
    return *(uint32_t*)&hp;
}
__device__ __forceinline__ float2 unpack_split(uint32_t hw, uint32_t lw) {
    __nv_bfloat162 hp = *(__nv_bfloat162*)&hw;
    __nv_bfloat162 lp = *(__nv_bfloat162*)&lw;
    return make_float2(__bfloat162float(hp.x) + __bfloat162float(lp.x),
                       __bfloat162float(hp.y) + __bfloat162float(lp.y));
}
__device__ __forceinline__ void store_split(char* ihi, char* ilo, int r, int c,
                                            float v0, float v1) {
    uint32_t lw, hw = split_pack(v0, v1, lw);
    uint32_t a = taddr(r, c);
    *(uint32_t*)(ihi + a) = hw; *(uint32_t*)(ilo + a) = lw;
}

// cp.async
__device__ __forceinline__ void cp16(uint32_t s, const void* g) {
    asm volatile("cp.async.cg.shared.global [%0], [%1], 16;" :: "r"(s), "l"(g) : "memory");
}
#define CP_COMMIT() asm volatile("cp.async.commit_group;" ::: "memory")
#define CP_WAIT0()  asm volatile("cp.async.wait_group 0;" ::: "memory")
#define CP_WAIT1()  asm volatile("cp.async.wait_group 1;" ::: "memory")
__device__ __forceinline__ void cpimg_h(uint32_t sdst, const char* g, int half, int tid) {
    uint32_t off = (uint32_t)half * HB;
    for (int i = tid; i < 1024; i += NTH) cp16(sdst + off + i * 16, g + off + i * 16);
}
__device__ __forceinline__ void cpimg(uint32_t sdst, const char* g, int tid) {
    for (int i = tid; i < 2048; i += NTH) cp16(sdst + i * 16, g + i * 16);
}

// ldmatrix / mma
__device__ __forceinline__ void ldsm4(uint32_t a[4], uint32_t addr) {
    asm volatile("ldmatrix.sync.aligned.m8n8.x4.shared.b16 {%0,%1,%2,%3}, [%4];"
        : "=r"(a[0]), "=r"(a[1]), "=r"(a[2]), "=r"(a[3]) : "r"(addr));
}
__device__ __forceinline__ void ldsm4t(uint32_t a[4], uint32_t addr) {
    asm volatile("ldmatrix.sync.aligned.m8n8.x4.trans.shared.b16 {%0,%1,%2,%3}, [%4];"
        : "=r"(a[0]), "=r"(a[1]), "=r"(a[2]), "=r"(a[3]) : "r"(addr));
}
__device__ __forceinline__ void mma16816(float c[4], const uint32_t a[4], const uint32_t* b) {
    asm volatile("mma.sync.aligned.m16n8k16.row.col.f32.bf16.bf16.f32 "
        "{%0,%1,%2,%3}, {%4,%5,%6,%7}, {%8,%9}, {%0,%1,%2,%3};"
        : "+f"(c[0]), "+f"(c[1]), "+f"(c[2]), "+f"(c[3])
        : "r"(a[0]), "r"(a[1]), "r"(a[2]), "r"(a[3]), "r"(b[0]), "r"(b[1]));
}

// one k-half (64 cols) of C[m][n] += A[m][k] B[n][k]; pass-separated MMA order.
__device__ __forceinline__ void gemm_h(uint32_t sAhi, uint32_t sAlo,
                                       uint32_t sBhi, uint32_t sBlo,
                                       float acc[2][4][4], int lane, int m0, int n0, int kbeg) {
#pragma unroll
    for (int k0 = kbeg; k0 < kbeg + 64; k0 += 16) {
        uint32_t aoff  = taddr(m0 + (lane & 15), k0 + ((lane >> 4) << 3));
        uint32_t aoff2 = taddr(m0 + 16 + (lane & 15), k0 + ((lane >> 4) << 3));
        uint32_t ah0[4], ah1[4], al0[4], al1[4];
        ldsm4(ah0, sAhi + aoff);  ldsm4(ah1, sAhi + aoff2);
        ldsm4(al0, sAlo + aoff);  ldsm4(al1, sAlo + aoff2);
        uint32_t bh[8], bl[8];
#pragma unroll
        for (int jj = 0; jj < 2; jj++) {
            uint32_t boff = taddr(n0 + jj * 16 + ((lane >> 4) << 3) + (lane & 7),
                                  k0 + (((lane >> 3) & 1) << 3));
            ldsm4(bh + jj * 4, sBhi + boff);
            ldsm4(bl + jj * 4, sBlo + boff);
        }
        // pass hh: 8 independent accumulators
#pragma unroll
        for (int j = 0; j < 4; j++) {
            mma16816(acc[0][j], ah0, bh + j * 2);
            mma16816(acc[1][j], ah1, bh + j * 2);
        }
        // pass hl
#pragma unroll
        for (int j = 0; j < 4; j++) {
            mma16816(acc[0][j], ah0, bl + j * 2);
            mma16816(acc[1][j], ah1, bl + j * 2);
        }
        // pass lh
#pragma unroll
        for (int j = 0; j < 4; j++) {
            mma16816(acc[0][j], al0, bh + j * 2);
            mma16816(acc[1][j], al1, bh + j * 2);
        }
    }
}

// one k-half (64 ROWS) of C[m][n] += A[t][m] B[t][n] (t-major, trans ldmatrix)
__device__ __forceinline__ void gemm_tt_h(uint32_t sAhi, uint32_t sAlo,
                                          uint32_t sBhi, uint32_t sBlo,
                                          float acc[2][4][4], int lane, int m0, int n0, int kbeg) {
#pragma unroll
    for (int k0 = kbeg; k0 < kbeg + 64; k0 += 16) {
        int arow = k0 + (lane & 7) + ((lane >> 4) << 3);
        int acol = ((lane >> 3) & 1) << 3;
        uint32_t aoff  = taddr(arow, m0 + acol);
        uint32_t aoff2 = taddr(arow, m0 + 16 + acol);
        uint32_t ah0[4], ah1[4], al0[4], al1[4];
        ldsm4t(ah0, sAhi + aoff);  ldsm4t(ah1, sAhi + aoff2);
        ldsm4t(al0, sAlo + aoff);  ldsm4t(al1, sAlo + aoff2);
        uint32_t bh[8], bl[8];
#pragma unroll
        for (int jj = 0; jj < 2; jj++) {
            uint32_t boff = taddr(k0 + (lane & 7) + (((lane >> 3) & 1) << 3),
                                  n0 + jj * 16 + ((lane >> 4) << 3));
            ldsm4t(bh + jj * 4, sBhi + boff);
            ldsm4t(bl + jj * 4, sBlo + boff);
        }
#pragma unroll
        for (int j = 0; j < 4; j++) {
            mma16816(acc[0][j], ah0, bh + j * 2);
            mma16816(acc[1][j], ah1, bh + j * 2);
        }
#pragma unroll
        for (int j = 0; j < 4; j++) {
            mma16816(acc[0][j], ah0, bl + j * 2);
            mma16816(acc[1][j], ah1, bl + j * 2);
        }
#pragma unroll
        for (int j = 0; j < 4; j++) {
            mma16816(acc[0][j], al0, bh + j * 2);
            mma16816(acc[1][j], al1, bh + j * 2);
        }
    }
}

// fused S-partial: part[tile][c][k] = sum_t hout[t][c] * B[t][k]
__device__ __forceinline__ void fused_reduce(uint32_t sHhi, uint32_t sHlo,
                                             uint32_t sTBhi, uint32_t sTBlo,
                                             int tile, int lane, int m0, int n0,
                                             int qr, int qc) {
    float acc[2][4][4] = {};
    gemm_tt_h(sHhi, sHlo, sTBhi, sTBlo, acc, lane, m0, n0, 0);
    gemm_tt_h(sHhi, sHlo, sTBhi, sTBlo, acc, lane, m0, n0, 64);
    size_t ob = (size_t)tile * D * KM;
#pragma unroll
    for (int mt = 0; mt < 2; mt++)
#pragma unroll
        for (int j = 0; j < 4; j++) {
            int row = m0 + mt * 16 + qr, col = n0 + j * 8 + qc;
            *(float2*)&g_part[ob + (size_t)row * KM + col]       = make_float2(acc[mt][j][0], acc[mt][j][1]);
            *(float2*)&g_part[ob + (size_t)(row + 8) * KM + col] = make_float2(acc[mt][j][2], acc[mt][j][3]);
        }
}

#define WARP_SETUP()                                                 \
    int tid = threadIdx.x;                                           \
    int lane = tid & 31, wid = tid >> 5;                             \
    int m0 = (wid & 3) * 32, n0 = (wid >> 2) * 32;                   \
    int qr = lane >> 2, qc = (lane & 3) * 2;                         \
    (void)qr; (void)qc;

#define TILE_PTRS(CS)                                                \
    extern __shared__ __align__(1024) char dsm[];                    \
    char* Ahi = dsm + OFF_AHI; char* Alo = dsm + OFF_ALO;            \
    char* Xhi = dsm + OFF_XHI; char* Xlo = dsm + OFF_XLO;            \
    uint32_t sb = smem_u32(dsm);                                     \
    uint32_t sAhi = sb + OFF_AHI, sAlo = sb + OFF_ALO;               \
    uint32_t sBhi = sb + OFF_BHI, sBlo = sb + OFF_BLO;               \
    float* ctrl = (float*)(dsm + (CS));                              \
    (void)Ahi; (void)Alo; (void)Xhi; (void)Xlo; (void)ctrl;

// ---------------- prep kernels -----------------------------------------------
__global__ void colb_kernel(const float* __restrict__ Bm) {
    int k = threadIdx.x, p = blockIdx.x;
    float s = 0.f;
    int r0 = p * 256;
    for (int r = 0; r < 256; r++) s += Bm[(r0 + r) * KM + k];
    g_colb[p * KM + k] = s;
}
__global__ void transpose_w_kernel(const float* __restrict__ W, int which) {
    float* Wt = which ? g_c3t : g_c1t;
    __shared__ float tile[32][33];
    int x0 = blockIdx.x * 32, y0 = blockIdx.y * 32;
    int tx = threadIdx.x, ty = threadIdx.y;
#pragma unroll
    for (int r = 0; r < 32; r += 8)
        tile[ty + r][tx] = W[(x0 + ty + r) * KM + y0 + tx];
    __syncthreads();
#pragma unroll
    for (int r = 0; r < 32; r += 8)
        Wt[(y0 + ty + r) * (D * D) + x0 + tx] = tile[tx][ty + r];
}
// split all 8 weight images: grid (32, 8)
__global__ void split_w_all_kernel(const float* __restrict__ w0, const float* __restrict__ w1,
                                   const float* __restrict__ w2, const float* __restrict__ w3,
                                   const float* __restrict__ w4, const float* __restrict__ w5,
                                   const float* __restrict__ w6, const float* __restrict__ w7) {
    int widx = blockIdx.y;
    const float* W;
    switch (widx) {
        case 0: W = w0; break; case 1: W = w1; break;
        case 2: W = w2; break; case 3: W = w3; break;
        case 4: W = w4; break; case 5: W = w5; break;
        case 6: W = w6; break; default: W = w7; break;
    }
    int p = blockIdx.x * 256 + threadIdx.x;
    int r = p >> 6, c = (p & 63) << 1;
    store_split(WIMG(widx, 0), WIMG(widx, 1), r, c, W[c * D + r], W[(c + 1) * D + r]);
}
__global__ void split_B_kernel(const float* __restrict__ Bm) {
    int tile = blockIdx.x;
    for (int p = threadIdx.x; p < 8192; p += 256) {
        int r = p >> 6, c = (p & 63) << 1;
        float2 v = *(const float2*)(Bm + (size_t)(tile * 128 + r) * KM + c);
        store_split(BIMG(tile, 0), BIMG(tile, 1), r, c, v.x, v.y);
    }
}
__global__ void reduce2_kernel() {
    int e = blockIdx.x * 256 + threadIdx.x;
    int b = blockIdx.y;
    const float* p = g_part + (size_t)b * 64 * D * KM + e;
    float s = 0.f;
#pragma unroll 8
    for (int t = 0; t < 64; t++) s += p[(size_t)t * D * KM];
    g_S[b * D * KM + e] = s;
}

#define AST 132
__device__ __forceinline__ void gemm8x8(const float* __restrict__ A, const float* __restrict__ W,
                                        float (&acc)[8][8], int ty, int tx, int kdim) {
    const float* ap = A + ty * 8;
    const float* wp = W + tx * 8;
#pragma unroll 4
    for (int k = 0; k < kdim; k++) {
        float4 a0 = *(const float4*)(ap + k * AST);
        float4 a1 = *(const float4*)(ap + k * AST + 4);
        float4 w0 = *(const float4*)(wp + k * AST);
        float4 w1 = *(const float4*)(wp + k * AST + 4);
        float a[8] = {a0.x,a0.y,a0.z,a0.w,a1.x,a1.y,a1.z,a1.w};
        float w[8] = {w0.x,w0.y,w0.z,w0.w,w1.x,w1.y,w1.z,w1.w};
#pragma unroll
        for (int i = 0; i < 8; i++)
#pragma unroll
            for (int j = 0; j < 8; j++)
                acc[i][j] = fmaf(a[i], w[j], acc[i][j]);
    }
}

__global__ void score_kernel(const float* __restrict__ wk, const float* __restrict__ bk) {
    extern __shared__ float sm[];
    float* As = sm;
    float* Ws = sm + D * AST;
    float* cb = Ws + D * AST;
    float* bks = cb + 128;
    int b = blockIdx.x, tid = threadIdx.x;
    if (tid < KM) {
        float s = 0.f;
        for (int p = 0; p < 32; p++) s += g_colb[p * KM + tid];
        cb[tid] = s;
        bks[tid] = bk[tid];
    }
    for (int idx = tid; idx < D * D; idx += 256) {
        As[(idx >> 7) * AST + (idx & 127)] = wk[idx];
        Ws[(idx >> 7) * AST + (idx & 127)] = g_S[b * D * KM + idx];
    }
    __syncthreads();
    int ty = tid >> 4, tx = tid & 15;
    float acc[8][8] = {};
    gemm8x8(As, Ws, acc, ty, tx, D);
#pragma unroll
    for (int j = 0; j < 8; j++) {
        int r = tx * 8 + j;
        float cbv = cb[r];
#pragma unroll
        for (int i = 0; i < 8; i += 2) {
            float v0 = acc[i][j]     + bks[ty * 8 + i]     * cbv;
            float v1 = acc[i + 1][j] + bks[ty * 8 + i + 1] * cbv;
            store_split(SCIMG(b, 0), SCIMG(b, 1), r, ty * 8 + i, v0, v1);
        }
    }
}

__global__ void gconv_modes_kernel(int which) {
    const float* Wt = which ? g_c3t : g_c1t;
    __shared__ float Ss[BB * D];
    int k = blockIdx.x, tid = threadIdx.x;
    for (int idx = tid; idx < BB * D; idx += 256)
        Ss[idx] = g_S[((idx >> 7) * D + (idx & 127)) * KM + k];
    __syncthreads();
    int hi = tid >> 7, o = tid & 127;
    float acc[8] = {};
    for (int i = 0; i < D; i++) {
        float w = Wt[(k * D + i) * D + o];
#pragma unroll
        for (int q = 0; q < 8; q++)
            acc[q] = fmaf(Ss[(hi * 8 + q) * D + i], w, acc[q]);
    }
    uint32_t a = taddr(o, k);
#pragma unroll
    for (int q = 0; q < 8; q++) {
        int bi = hi * 8 + q;
        __nv_bfloat16 hb = __float2bfloat16(acc[q]);
        __nv_bfloat16 lb = __float2bfloat16(acc[q] - __bfloat162float(hb));
        *(uint16_t*)(SCIMG(bi, 0) + a) = *(uint16_t*)&hb;
        *(uint16_t*)(SCIMG(bi, 1) + a) = *(uint16_t*)&lb;
    }
}

// ---------------- fc0 (+ fused S partial) -------------------------------------
__global__ __launch_bounds__(NTH, 1)
void fc0_kernel(const float* __restrict__ x, const float* __restrict__ w1,
                const float* __restrict__ b1, const float* __restrict__ b2) {
    TILE_PTRS(CS_MID); WARP_SETUP();
    float* xs  = ctrl;
    float* w1s = ctrl + 256;
    float* b1s = ctrl + 512;
    float* b2s = ctrl + 640;
    int tile = blockIdx.x;
    int tok0 = tile * 128;
    int tb = tile & 63;

    cpimg_h(sBhi, WIMG(0, 0), 0, tid); cpimg_h(sBlo, WIMG(0, 1), 0, tid); CP_COMMIT();
    cpimg_h(sBhi, WIMG(0, 0), 1, tid); cpimg_h(sBlo, WIMG(0, 1), 1, tid); CP_COMMIT();
    if (tid < 256) { xs[tid] = x[tok0 * 2 + tid]; w1s[tid] = w1[tid]; }
    if (tid < 128) { b1s[tid] = b1[tid]; b2s[tid] = b2[tid]; }
    __syncthreads();

    for (int p = tid; p < 128 * 64; p += NTH) {
        int r = p >> 6, c = (p & 63) << 1;
        float v0 = gelu_f(xs[2*r] * w1s[c]   + xs[2*r+1] * w1s[128+c]   + b1s[c]);
        float v1 = gelu_f(xs[2*r] * w1s[c+1] + xs[2*r+1] * w1s[128+c+1] + b1s[c+1]);
        uint32_t lw, hw = split_pack(v0, v1, lw);
        uint32_t a = taddr(r, c);
        *(uint32_t*)(Ahi + a) = hw; *(uint32_t*)(Alo + a) = lw;
    }
    CP_WAIT1(); __syncthreads();

    float acc[2][4][4] = {};
    gemm_h(sAhi, sAlo, sBhi, sBlo, acc, lane, m0, n0, 0);
    CP_WAIT0(); __syncthreads();
    gemm_h(sAhi, sAlo, sBhi, sBlo, acc, lane, m0, n0, 64);
    __syncthreads();

    cpimg(sBhi, BIMG(tb, 0), tid); cpimg(sBlo, BIMG(tb, 1), tid); CP_COMMIT();

    char* oh = HIMG(tile, 0); char* ol = HIMG(tile, 1);
#pragma unroll
    for (int mt = 0; mt < 2; mt++)
#pragma unroll
        for (int j = 0; j < 4; j++) {
            int row = m0 + mt * 16 + qr, col = n0 + j * 8 + qc;
#pragma unroll
            for (int h = 0; h < 2; h++) {
                int r = row + h * 8;
                float o0 = acc[mt][j][2*h]   + b2s[col];
                float o1 = acc[mt][j][2*h+1] + b2s[col + 1];
                uint32_t lw, hw = split_pack(o0, o1, lw);
                uint32_t a = taddr(r, col);
                *(uint32_t*)(oh + a) = hw;  *(uint32_t*)(ol + a) = lw;
                *(uint32_t*)(Ahi + a) = hw; *(uint32_t*)(Alo + a) = lw;
            }
        }
    CP_WAIT0(); __syncthreads();
    fused_reduce(sAhi, sAlo, sBhi, sBlo, tile, lane, m0, n0, qr, qc);
}

// ---------------- attention map (3 chained GEMMs + fused S) ------------------
__global__ __launch_bounds__(NTH, 1)
void attn_map_kernel(int wbase, const float* __restrict__ f1b, const float* __restrict__ f2b) {
    TILE_PTRS(CS_BIG); WARP_SETUP();
    uint32_t sXhi = sb + OFF_XHI, sXlo = sb + OFF_XLO;
    int b = blockIdx.x >> 6;
    int tile = blockIdx.x;
    int tb = tile & 63;

    if (tid < 128) { ctrl[tid] = f1b[tid]; ctrl[128 + tid] = f2b[tid]; }
    cpimg_h(sAhi, BIMG(tb, 0), 0, tid); cpimg_h(sAlo, BIMG(tb, 1), 0, tid);
    cpimg_h(sBhi, SCIMG(b, 0), 0, tid); cpimg_h(sBlo, SCIMG(b, 1), 0, tid);
    CP_COMMIT();
    cpimg_h(sAhi, BIMG(tb, 0), 1, tid); cpimg_h(sAlo, BIMG(tb, 1), 1, tid);
    cpimg_h(sBhi, SCIMG(b, 0), 1, tid); cpimg_h(sBlo, SCIMG(b, 1), 1, tid);
    cpimg(sXhi, HIMG(tile, 0), tid);    cpimg(sXlo, HIMG(tile, 1), tid);
    CP_COMMIT();

    float acc[2][4][4] = {};
    CP_WAIT1(); __syncthreads();
    gemm_h(sAhi, sAlo, sBhi, sBlo, acc, lane, m0, n0, 0);
    __syncthreads();
    cpimg_h(sBhi, WIMG(wbase, 0), 0, tid); cpimg_h(sBlo, WIMG(wbase, 1), 0, tid); CP_COMMIT();
    CP_WAIT1(); __syncthreads();
    gemm_h(sAhi, sAlo, sBhi, sBlo, acc, lane, m0, n0, 64);
    __syncthreads();
    cpimg_h(sBhi, WIMG(wbase, 0), 1, tid); cpimg_h(sBlo, WIMG(wbase, 1), 1, tid); CP_COMMIT();

#pragma unroll
    for (int mt = 0; mt < 2; mt++)
#pragma unroll
        for (int j = 0; j < 4; j++) {
            int row = m0 + mt * 16 + qr, col = n0 + j * 8 + qc;
#pragma unroll
            for (int h = 0; h < 2; h++) {
                int r = row + h * 8;
                uint32_t a = taddr(r, col);
                float2 hh = unpack_split(*(uint32_t*)(Xhi + a), *(uint32_t*)(Xlo + a));
                float x0 = gelu_f(acc[mt][j][2*h])   + hh.x;
                float x1 = gelu_f(acc[mt][j][2*h+1]) + hh.y;
                uint32_t lw, hw = split_pack(x0, x1, lw);
                *(uint32_t*)(Ahi + a) = hw; *(uint32_t*)(Alo + a) = lw;
                *(uint32_t*)(Xhi + a) = hw; *(uint32_t*)(Xlo + a) = lw;
            }
        }

    float acc2[2][4][4] = {};
    CP_WAIT1(); __syncthreads();
    gemm_h(sAhi, sAlo, sBhi, sBlo, acc2, lane, m0, n0, 0);
    __syncthreads();
    cpimg_h(sBhi, WIMG(wbase + 1, 0), 0, tid); cpimg_h(sBlo, WIMG(wbase + 1, 1), 0, tid); CP_COMMIT();
    CP_WAIT1(); __syncthreads();
    gemm_h(sAhi, sAlo, sBhi, sBlo, acc2, lane, m0, n0, 64);
    __syncthreads();
    cpimg_h(sBhi, WIMG(wbase + 1, 0), 1, tid); cpimg_h(sBlo, WIMG(wbase + 1, 1), 1, tid); CP_COMMIT();

#pragma unroll
    for (int mt = 0; mt < 2; mt++)
#pragma unroll
        for (int j = 0; j < 4; j++) {
            int row = m0 + mt * 16 + qr, col = n0 + j * 8 + qc;
#pragma unroll
            for (int h = 0; h < 2; h++) {
                int r = row + h * 8;
                float g0 = gelu_f(acc2[mt][j][2*h]   + ctrl[col]);
                float g1 = gelu_f(acc2[mt][j][2*h+1] + ctrl[col + 1]);
                uint32_t lw, hw = split_pack(g0, g1, lw);
                uint32_t a = taddr(r, col);
                *(uint32_t*)(Ahi + a) = hw; *(uint32_t*)(Alo + a) = lw;
            }
        }

    float acc3[2][4][4] = {};
    CP_WAIT1(); __syncthreads();
    gemm_h(sAhi, sAlo, sBhi, sBlo, acc3, lane, m0, n0, 0);
    CP_WAIT0(); __syncthreads();
    gemm_h(sAhi, sAlo, sBhi, sBlo, acc3, lane, m0, n0, 64);
    __syncthreads();

    cpimg(sAhi, BIMG(tb, 0), tid); cpimg(sAlo, BIMG(tb, 1), tid); CP_COMMIT();

    char* oh = HIMG(tile, 0); char* ol = HIMG(tile, 1);
#pragma unroll
    for (int mt = 0; mt < 2; mt++)
#pragma unroll
        for (int j = 0; j < 4; j++) {
            int row = m0 + mt * 16 + qr, col = n0 + j * 8 + qc;
#pragma unroll
            for (int h = 0; h < 2; h++) {
                int r = row + h * 8;
                uint32_t a = taddr(r, col);
                float2 xt = unpack_split(*(uint32_t*)(Xhi + a), *(uint32_t*)(Xlo + a));
                float o0 = xt.x + acc3[mt][j][2*h]   + ctrl[128 + col];
                float o1 = xt.y + acc3[mt][j][2*h+1] + ctrl[128 + col + 1];
                uint32_t lw, hw = split_pack(o0, o1, lw);
                *(uint32_t*)(oh + a) = hw;  *(uint32_t*)(ol + a) = lw;
                *(uint32_t*)(Xhi + a) = hw; *(uint32_t*)(Xlo + a) = lw;
            }
        }
    CP_WAIT0(); __syncthreads();
    fused_reduce(sXhi, sXlo, sAhi, sAlo, tile, lane, m0, n0, qr, qc);
}

// ---------------- gconv map (2 GEMMs + optional fused S) ---------------------
__global__ __launch_bounds__(NTH, 1)
void gconv_map_kernel(int widx, const float* __restrict__ wb, int act, int do_red) {
    TILE_PTRS(CS_MID); WARP_SETUP();
    int b = blockIdx.x >> 6;
    int tile = blockIdx.x;
    int tb = tile & 63;

    if (tid < 128) ctrl[tid] = wb[tid];
    cpimg_h(sAhi, BIMG(tb, 0), 0, tid); cpimg_h(sAlo, BIMG(tb, 1), 0, tid);
    cpimg_h(sBhi, SCIMG(b, 0), 0, tid); cpimg_h(sBlo, SCIMG(b, 1), 0, tid);
    CP_COMMIT();
    cpimg_h(sAhi, BIMG(tb, 0), 1, tid); cpimg_h(sAlo, BIMG(tb, 1), 1, tid);
    cpimg_h(sBhi, SCIMG(b, 0), 1, tid); cpimg_h(sBlo, SCIMG(b, 1), 1, tid);
    CP_COMMIT();

    float acc[2][4][4] = {};
    CP_WAIT1(); __syncthreads();
    gemm_h(sAhi, sAlo, sBhi, sBlo, acc, lane, m0, n0, 0);
    __syncthreads();
    cpimg_h(sAhi, HIMG(tile, 0), 0, tid); cpimg_h(sAlo, HIMG(tile, 1), 0, tid);
    cpimg_h(sBhi, WIMG(widx, 0), 0, tid); cpimg_h(sBlo, WIMG(widx, 1), 0, tid);
    CP_COMMIT();
    CP_WAIT1(); __syncthreads();
    gemm_h(sAhi, sAlo, sBhi, sBlo, acc, lane, m0, n0, 64);
    __syncthreads();
    cpimg_h(sAhi, HIMG(tile, 0), 1, tid); cpimg_h(sAlo, HIMG(tile, 1), 1, tid);
    cpimg_h(sBhi, WIMG(widx, 0), 1, tid); cpimg_h(sBlo, WIMG(widx, 1), 1, tid);
    CP_COMMIT();
    CP_WAIT1(); __syncthreads();
    gemm_h(sAhi, sAlo, sBhi, sBlo, acc, lane, m0, n0, 0);
    CP_WAIT0(); __syncthreads();
    gemm_h(sAhi, sAlo, sBhi, sBlo, acc, lane, m0, n0, 64);
    __syncthreads();

    if (do_red) { cpimg(sBhi, BIMG(tb, 0), tid); cpimg(sBlo, BIMG(tb, 1), tid); CP_COMMIT(); }

    char* oh = HIMG(tile, 0); char* ol = HIMG(tile, 1);
#pragma unroll
    for (int mt = 0; mt < 2; mt++)
#pragma unroll
        for (int j = 0; j < 4; j++) {
            int row = m0 + mt * 16 + qr, col = n0 + j * 8 + qc;
#pragma unroll
            for (int h = 0; h < 2; h++) {
                int r = row + h * 8;
                uint32_t a = taddr(r, col);
                float2 hh = unpack_split(*(uint32_t*)(Ahi + a), *(uint32_t*)(Alo + a));
                float z0 = acc[mt][j][2*h]   + ctrl[col];
                float z1 = acc[mt][j][2*h+1] + ctrl[col + 1];
                if (act) { z0 = gelu_f(z0); z1 = gelu_f(z1); }
                float o0 = hh.x + z0, o1 = hh.y + z1;
                uint32_t lw, hw = split_pack(o0, o1, lw);
                *(uint32_t*)(oh + a) = hw;  *(uint32_t*)(ol + a) = lw;
                *(uint32_t*)(Ahi + a) = hw; *(uint32_t*)(Alo + a) = lw;
            }
        }
    if (do_red) {
        CP_WAIT0(); __syncthreads();
        fused_reduce(sAhi, sAlo, sBhi, sBlo, tile, lane, m0, n0, qr, qc);
    }
}

// ---------------- head --------------------------------------------------------
__global__ __launch_bounds__(NTH, 1)
void head_kernel(const float* __restrict__ fc1b, const float* __restrict__ fc2w,
                 const float* __restrict__ fc2b, float* __restrict__ out) {
    TILE_PTRS(CS_MID); WARP_SETUP();
    int tile = blockIdx.x;
    size_t tok0 = (size_t)tile * 128;
    int wn = wid >> 2;

    if (tid < 128) { ctrl[tid] = fc1b[tid]; ctrl[128 + tid] = fc2w[tid]; }
    float* partial = ctrl + 256;
    cpimg_h(sAhi, HIMG(tile, 0), 0, tid); cpimg_h(sAlo, HIMG(tile, 1), 0, tid);
    cpimg_h(sBhi, WIMG(7, 0), 0, tid);    cpimg_h(sBlo, WIMG(7, 1), 0, tid);
    CP_COMMIT();
    cpimg_h(sAhi, HIMG(tile, 0), 1, tid); cpimg_h(sAlo, HIMG(tile, 1), 1, tid);
    cpimg_h(sBhi, WIMG(7, 0), 1, tid);    cpimg_h(sBlo, WIMG(7, 1), 1, tid);
    CP_COMMIT();

    float acc[2][4][4] = {};
    CP_WAIT1(); __syncthreads();
    gemm_h(sAhi, sAlo, sBhi, sBlo, acc, lane, m0, n0, 0);
    CP_WAIT0(); __syncthreads();
    gemm_h(sAhi, sAlo, sBhi, sBlo, acc, lane, m0, n0, 64);

    float s[2][2] = {};
#pragma unroll
    for (int mt = 0; mt < 2; mt++)
#pragma unroll
        for (int j = 0; j < 4; j++) {
            int col = n0 + j * 8 + qc;
            s[mt][0] += gelu_f(acc[mt][j][0] + ctrl[col])     * ctrl[128 + col]
                      + gelu_f(acc[mt][j][1] + ctrl[col + 1]) * ctrl[128 + col + 1];
            s[mt][1] += gelu_f(acc[mt][j][2] + ctrl[col])     * ctrl[128 + col]
                      + gelu_f(acc[mt][j][3] + ctrl[col + 1]) * ctrl[128 + col + 1];
        }
#pragma unroll
    for (int mt = 0; mt < 2; mt++)
#pragma unroll
        for (int h = 0; h < 2; h++) {
            s[mt][h] += __shfl_xor_sync(0xffffffffu, s[mt][h], 1);
            s[mt][h] += __shfl_xor_sync(0xffffffffu, s[mt][h], 2);
        }
    if ((lane & 3) == 0) {
#pragma unroll
        for (int mt = 0; mt < 2; mt++) {
            partial[wn * 128 + m0 + mt * 16 + qr]     = s[mt][0];
            partial[wn * 128 + m0 + mt * 16 + qr + 8] = s[mt][1];
        }
    }
    __syncthreads();
    if (tid < 128)
        out[tok0 + tid] = partial[tid] + partial[128 + tid] + partial[256 + tid]
                        + partial[384 + tid] + fc2b[0];
}

// ---------------- launch ------------------------------------------------------
extern "C" void kernel_launch(void* const* d_in, const int* in_sizes, int n_in,
                              void* d_out, int out_size) {
    const float* x      = (const float*)d_in[0];
    const float* Bm     = (const float*)d_in[1];
    const float* fc0_w1 = (const float*)d_in[2];
    const float* fc0_b1 = (const float*)d_in[3];
    const float* fc0_w2 = (const float*)d_in[4];
    const float* fc0_b2 = (const float*)d_in[5];
    const float* a0_wk  = (const float*)d_in[6];
    const float* a0_bk  = (const float*)d_in[7];
    const float* a0_f1w = (const float*)d_in[8];
    const float* a0_f1b = (const float*)d_in[9];
    const float* a0_f2w = (const float*)d_in[10];
    const float* a0_f2b = (const float*)d_in[11];
    const float* c1_w   = (const float*)d_in[12];
    const float* w1_w   = (const float*)d_in[13];
    const float* w1_b   = (const float*)d_in[14];
    const float* a2_wk  = (const float*)d_in[15];
    const float* a2_bk  = (const float*)d_in[16];
    const float* a2_f1w = (const float*)d_in[17];
    const float* a2_f1b = (const float*)d_in[18];
    const float* a2_f2w = (const float*)d_in[19];
    const float* a2_f2b = (const float*)d_in[20];
    const float* c3_w   = (const float*)d_in[21];
    const float* w3_w   = (const float*)d_in[22];
    const float* w3_b   = (const float*)d_in[23];
    const float* fc1_w  = (const float*)d_in[24];
    const float* fc1_b  = (const float*)d_in[25];
    const float* fc2_w  = (const float*)d_in[26];
    const float* fc2_b  = (const float*)d_in[27];
    float* out = (float*)d_out;

    const int SM2 = (2 * D * AST + 1024) * sizeof(float);
    cudaFuncSetAttribute((const void*)fc0_kernel,       cudaFuncAttributeMaxDynamicSharedMemorySize, SM_MID);
    cudaFuncSetAttribute((const void*)attn_map_kernel,  cudaFuncAttributeMaxDynamicSharedMemorySize, SM_BIG);
    cudaFuncSetAttribute((const void*)gconv_map_kernel, cudaFuncAttributeMaxDynamicSharedMemorySize, SM_MID);
    cudaFuncSetAttribute((const void*)head_kernel,      cudaFuncAttributeMaxDynamicSharedMemorySize, SM_MID);
    cudaFuncSetAttribute((const void*)score_kernel,     cudaFuncAttributeMaxDynamicSharedMemorySize, SM2);

    // exactly 5 prep launches so fc0 is launch #6 (ncu -s 5 -c 1 captures it)
    colb_kernel<<<32, 128>>>(Bm);
    split_B_kernel<<<64, 256>>>(Bm);
    transpose_w_kernel<<<dim3(512, 4), dim3(32, 8)>>>(c1_w, 0);
    transpose_w_kernel<<<dim3(512, 4), dim3(32, 8)>>>(c3_w, 1);
    split_w_all_kernel<<<dim3(32, 8), 256>>>(fc0_w2, a0_f1w, a0_f2w, w1_w,
                                             a2_f1w, a2_f2w, w3_w, fc1_w);

    fc0_kernel<<<NTILES, NTH, SM_MID>>>(x, fc0_w1, fc0_b1, fc0_b2);

    reduce2_kernel<<<dim3(64, BB), 256>>>();
    score_kernel<<<BB, 256, SM2>>>(a0_wk, a0_bk);
    attn_map_kernel<<<NTILES, NTH, SM_BIG>>>(1, a0_f1b, a0_f2b);

    reduce2_kernel<<<dim3(64, BB), 256>>>();
    gconv_modes_kernel<<<KM, 256>>>(0);
    gconv_map_kernel<<<NTILES, NTH, SM_MID>>>(3, w1_b, 1, 1);

    reduce2_kernel<<<dim3(64, BB), 256>>>();
    score_kernel<<<BB, 256, SM2>>>(a2_wk, a2_bk);
    attn_map_kernel<<<NTILES, NTH, SM_BIG>>>(4, a2_f1b, a2_f2b);

    reduce2_kernel<<<dim3(64, BB), 256>>>();
    gconv_modes_kernel<<<KM, 256>>>(1);
    gconv_map_kernel<<<NTILES, NTH, SM_MID>>>(6, w3_b, 0, 0);

    head_kernel<<<NTILES, NTH, SM_MID>>>(fc1_b, fc2_w, fc2_b, out);
}